// round 13
// baseline (speedup 1.0000x reference)
#include <cuda_runtime.h>
#include <cstdint>

// ---------------------------------------------------------------------------
// GraphConvLayer — mma.sync tf32, 4-deep cp.async, 512-thread GEMM CTA
//   0) prep_kernel   : transpose weights -> tf32 [n][k]
//   1) gather_all    : all-degree atom-sum + bond-sum (single launch)
//   2) gemm_mma      : ONE launch, 5 segments; 128x256x512 per CTA,
//                      16 warps (4/SMSP), warp tile 32x64, 4-slot cp.async,
//                      bias+bond epilogue + ReLU -> g_pre, per-CTA bn stats
//   3) stats_reduce / finalize : deterministic batchnorm scale/shift
//   4) norm_kernel   : g_pre -> d_out
// ---------------------------------------------------------------------------

#define NATOMS_MAX 200000
#define MAX_SLOTS 2048
#define QOFF (MAX_SLOTS * 256)

__device__ float g_Asum[(size_t)NATOMS_MAX * 256];
__device__ float g_Bsum[(size_t)NATOMS_MAX * 8];
__device__ float g_pre [(size_t)NATOMS_MAX * 256];
__device__ float g_Wt_self[256 * 256];        // [n][k], tf32-rounded
__device__ float g_Wt_deg [5 * 256 * 256];    // [d][n][k]
__device__ float g_part [2 * MAX_SLOTS * 256];
__device__ float g_part2[2 * 64 * 256];
__device__ float g_scale[256];
__device__ float g_shift[256];

// ---------------- helpers ----------------
__device__ __forceinline__ uint32_t smem_u32(const void* p) {
    uint32_t a;
    asm("{ .reg .u64 t; cvta.to.shared.u64 t, %1; cvt.u32.u64 %0, t; }"
        : "=r"(a) : "l"(p));
    return a;
}
__device__ __forceinline__ uint32_t f2tf(float f) {
    uint32_t u;
    asm("cvt.rna.tf32.f32 %0, %1;" : "=r"(u) : "f"(f));
    return u;
}
__device__ __forceinline__ void cp_async16(uint32_t saddr, const void* gptr) {
    size_t g = __cvta_generic_to_global(gptr);
    asm volatile("cp.async.cg.shared.global [%0], [%1], 16;"
                 :: "r"(saddr), "l"(g));
}
#define CP_COMMIT() asm volatile("cp.async.commit_group;" ::: "memory")
#define CP_WAIT2()  asm volatile("cp.async.wait_group 2;" ::: "memory")

__device__ __forceinline__ void ldm_x4(uint32_t* r, uint32_t addr) {
    asm volatile("ldmatrix.sync.aligned.m8n8.x4.shared.b16 {%0,%1,%2,%3}, [%4];"
                 : "=r"(r[0]), "=r"(r[1]), "=r"(r[2]), "=r"(r[3]) : "r"(addr));
}
__device__ __forceinline__ void mma_tf32(float* c, const uint32_t* a,
                                         uint32_t b0, uint32_t b1) {
    asm volatile(
        "mma.sync.aligned.m16n8k8.row.col.f32.tf32.tf32.f32 "
        "{%0,%1,%2,%3}, {%4,%5,%6,%7}, {%8,%9}, {%0,%1,%2,%3};"
        : "+f"(c[0]), "+f"(c[1]), "+f"(c[2]), "+f"(c[3])
        : "r"(a[0]), "r"(a[1]), "r"(a[2]), "r"(a[3]), "r"(b0), "r"(b1));
}

// ---------------------------------------------------------------------------
// 0) prep: Wt[n][k] = tf32(W[k][n])
// ---------------------------------------------------------------------------
__global__ void __launch_bounds__(256) prep_kernel(
    const float* __restrict__ Ws,
    const float* __restrict__ W1, const float* __restrict__ W2,
    const float* __restrict__ W3, const float* __restrict__ W4,
    const float* __restrict__ W5)
{
    const float* Wd[5] = {W1, W2, W3, W4, W5};
    int id = blockIdx.x * 256 + threadIdx.x;
    if (id < 65536) {
        int n = id >> 8, k = id & 255;
        g_Wt_self[id] = __uint_as_float(f2tf(__ldg(Ws + k * 256 + n)));
    } else if (id < 6 * 65536) {
        int t = id - 65536;
        int d = t >> 16, rr = t & 65535;
        int n = rr >> 8, k = rr & 255;
        g_Wt_deg[t] = __uint_as_float(f2tf(__ldg(Wd[d] + k * 256 + n)));
    }
}

// ---------------------------------------------------------------------------
// 1) gather (single launch, block-range dispatch over 5+5 segments)
// ---------------------------------------------------------------------------
struct GArgs {
    const int* an[5];
    const int* bn[5];
    int nd[5];
    int off[5];
    int blkA[6];
    int blkB[6];
};

template <int D>
__device__ __forceinline__ void do_atoms(const float* __restrict__ af,
                                         const int* __restrict__ anbr,
                                         int row_start, int n, int lb)
{
    int gid = lb * 256 + threadIdx.x;
    int atom = gid >> 6;
    if (atom >= n) return;
    int c = gid & 63;
    int idx[D];
#pragma unroll
    for (int s = 0; s < D; ++s) idx[s] = __ldg(anbr + atom * D + s);
    float4 acc = make_float4(0.f, 0.f, 0.f, 0.f);
#pragma unroll
    for (int s = 0; s < D; ++s) {
        float4 v = __ldg((const float4*)af + (size_t)idx[s] * 64 + c);
        acc.x += v.x; acc.y += v.y; acc.z += v.z; acc.w += v.w;
    }
    acc.x = __uint_as_float(f2tf(acc.x));
    acc.y = __uint_as_float(f2tf(acc.y));
    acc.z = __uint_as_float(f2tf(acc.z));
    acc.w = __uint_as_float(f2tf(acc.w));
    ((float4*)g_Asum)[(size_t)(row_start + atom) * 64 + c] = acc;
}

template <int D>
__device__ __forceinline__ void do_bonds(const float* __restrict__ bf,
                                         const int* __restrict__ bnbr,
                                         int row_start, int n, int lb)
{
    int atom = lb * 256 + threadIdx.x;
    if (atom >= n) return;
    float s[6] = {0.f, 0.f, 0.f, 0.f, 0.f, 0.f};
#pragma unroll
    for (int j = 0; j < D; ++j) {
        int idx = __ldg(bnbr + atom * D + j);
        const float* row = bf + (size_t)idx * 6;
#pragma unroll
        for (int q = 0; q < 6; ++q) s[q] += __ldg(row + q);
    }
    float* o = g_Bsum + (size_t)(row_start + atom) * 8;
    *(float4*)o       = make_float4(s[0], s[1], s[2], s[3]);
    *(float4*)(o + 4) = make_float4(s[4], s[5], 0.f, 0.f);
}

__global__ void __launch_bounds__(256) gather_all(
    const float* __restrict__ af, const float* __restrict__ bf, GArgs ga)
{
    int bid = blockIdx.x;
    if (bid < ga.blkA[5]) {
        int d = 0;
        while (bid >= ga.blkA[d + 1]) ++d;
        int lb = bid - ga.blkA[d];
        switch (d) {
        case 0: do_atoms<1>(af, ga.an[0], ga.off[0], ga.nd[0], lb); break;
        case 1: do_atoms<2>(af, ga.an[1], ga.off[1], ga.nd[1], lb); break;
        case 2: do_atoms<3>(af, ga.an[2], ga.off[2], ga.nd[2], lb); break;
        case 3: do_atoms<4>(af, ga.an[3], ga.off[3], ga.nd[3], lb); break;
        default: do_atoms<5>(af, ga.an[4], ga.off[4], ga.nd[4], lb); break;
        }
    } else {
        int bb = bid - ga.blkA[5];
        int d = 0;
        while (bb >= ga.blkB[d + 1]) ++d;
        int lb = bb - ga.blkB[d];
        switch (d) {
        case 0: do_bonds<1>(bf, ga.bn[0], ga.off[0], ga.nd[0], lb); break;
        case 1: do_bonds<2>(bf, ga.bn[1], ga.off[1], ga.nd[1], lb); break;
        case 2: do_bonds<3>(bf, ga.bn[2], ga.off[2], ga.nd[2], lb); break;
        case 3: do_bonds<4>(bf, ga.bn[3], ga.off[3], ga.nd[3], lb); break;
        default: do_bonds<5>(bf, ga.bn[4], ga.off[4], ga.nd[4], lb); break;
        }
    }
}

// ---------------------------------------------------------------------------
// 2) merged GEMM, 512 threads: CTA 128(M) x 256(N), K=512, 16 stages of 32.
//    16 warps = 4(M) x 4(N); warp tile 32x64; m16n8k8 tf32 (ldmatrix b16).
//    4-slot cp.async (distance 3); smem A 4x16KB @ uS, B 4x32KB @ uS+65536.
// ---------------------------------------------------------------------------
struct SegArgs {
    const float* Worig[5];   // original [262][256] (bond rows)
    int blk[6];              // cumulative CTA offsets per segment
    int off[5];
    int nd[5];
};

__device__ __forceinline__ void issue_stage(
    uint32_t uS, int slot, int kt,
    const float* __restrict__ af, const float* __restrict__ WtD,
    int tid, int m0, int row_start, int n_rows)
{
    const int lrow = tid >> 3;          // 0..63
    const int lchk = tid & 7;
    const int kk = (kt * 32) & 255;

    const float* Ab = (kt < 8) ? af : g_Asum;
    uint32_t dA = uS + (uint32_t)slot * 16384;
#pragma unroll
    for (int p = 0; p < 2; ++p) {
        int r = lrow + p * 64;
        int rg = m0 + r; if (rg >= n_rows) rg = n_rows - 1;
        const char* src = (const char*)(Ab + (size_t)(row_start + rg) * 256 + kk)
                          + lchk * 16;
        cp_async16(dA + (uint32_t)r * 128 + (uint32_t)((lchk ^ (r & 7)) << 4), src);
    }
    const float* Bb = (kt < 8) ? g_Wt_self : WtD;
    uint32_t dB = uS + 65536u + (uint32_t)slot * 32768;
#pragma unroll
    for (int p = 0; p < 4; ++p) {
        int r = lrow + p * 64;
        const char* src = (const char*)(Bb + (size_t)r * 256 + kk) + lchk * 16;
        cp_async16(dB + (uint32_t)r * 128 + (uint32_t)((lchk ^ (r & 7)) << 4), src);
    }
}

__global__ void __launch_bounds__(512, 1) gemm_mma(
    const float* __restrict__ af, const float* __restrict__ bias, SegArgs sa)
{
    extern __shared__ float dsm[];          // 4*(16KB A) + 4*(32KB B) = 192KB
    __shared__ float s_wbot[6][256];
    __shared__ float s_bias[256];
    __shared__ float s_ws[4][256];          // cross-warp stats merge (sum)
    __shared__ float s_wq[4][256];          // (sumsq)

    // ---- segment dispatch ----
    int deg = 0;
    while ((int)blockIdx.x >= sa.blk[deg + 1]) ++deg;
    const int m0 = (blockIdx.x - sa.blk[deg]) * 128;
    const int row_start = sa.off[deg];
    const int n_rows = sa.nd[deg];
    const float* __restrict__ Worig = sa.Worig[deg];
    const float* __restrict__ WtD = g_Wt_deg + (size_t)deg * 65536;

    const uint32_t uS = smem_u32(dsm);
    const int tid = threadIdx.x;
    const int warp = tid >> 5, lane = tid & 31;
    const int wm = (warp & 3) * 32;         // M warp group
    const int wn = (warp >> 2) * 64;        // N warp group

    if (tid < 256) s_bias[tid] = __ldg(bias + tid);
#pragma unroll
    for (int j = 0; j < 3; ++j) {
        int jj2 = j * 2 + (tid >> 8);
        s_wbot[jj2][tid & 255] = __ldg(Worig + (size_t)(256 + jj2) * 256 + (tid & 255));
    }

    float acc[2][8][4];
#pragma unroll
    for (int a = 0; a < 2; ++a)
#pragma unroll
        for (int b = 0; b < 8; ++b)
#pragma unroll
            for (int e = 0; e < 4; ++e) acc[a][b][e] = 0.f;

    const int jj = lane >> 3, rr = lane & 7;
    uint32_t rowA[2], rowB[4];
#pragma unroll
    for (int mt = 0; mt < 2; ++mt)
        rowA[mt] = (uint32_t)(wm + mt * 16 + (jj & 1) * 8 + rr) * 128;
#pragma unroll
    for (int np = 0; np < 4; ++np)
        rowB[np] = (uint32_t)(wn + np * 16 + (jj >> 1) * 8 + rr) * 128;
    const int cjA = jj >> 1, cjB = jj & 1;

    issue_stage(uS, 0, 0, af, WtD, tid, m0, row_start, n_rows); CP_COMMIT();
    issue_stage(uS, 1, 1, af, WtD, tid, m0, row_start, n_rows); CP_COMMIT();
    issue_stage(uS, 2, 2, af, WtD, tid, m0, row_start, n_rows); CP_COMMIT();

    for (int kt = 0; kt < 16; ++kt) {
        CP_WAIT2();
        __syncthreads();
        if (kt + 3 < 16)
            issue_stage(uS, (kt + 3) & 3, kt + 3, af, WtD, tid, m0, row_start, n_rows);
        CP_COMMIT();

        const uint32_t baseA = uS + (uint32_t)(kt & 3) * 16384;
        const uint32_t baseB = uS + 65536u + (uint32_t)(kt & 3) * 32768;
#pragma unroll
        for (int k8 = 0; k8 < 4; ++k8) {
            uint32_t aF[2][4], bF[4][4];
            const uint32_t ca = (uint32_t)(((2 * k8 + cjA) ^ rr) << 4);
            const uint32_t cb = (uint32_t)(((2 * k8 + cjB) ^ rr) << 4);
#pragma unroll
            for (int mt = 0; mt < 2; ++mt) ldm_x4(aF[mt], baseA + rowA[mt] + ca);
#pragma unroll
            for (int np = 0; np < 4; ++np) ldm_x4(bF[np], baseB + rowB[np] + cb);
#pragma unroll
            for (int mt = 0; mt < 2; ++mt)
#pragma unroll
                for (int np = 0; np < 4; ++np) {
                    mma_tf32(acc[mt][2 * np],     aF[mt], bF[np][0], bF[np][1]);
                    mma_tf32(acc[mt][2 * np + 1], aF[mt], bF[np][2], bF[np][3]);
                }
        }
    }

    // ---- epilogue: + bias + Bsum@wbot, ReLU, store, column stats ----
    const int g = lane >> 2, tq = lane & 3;
    float st_s[16], st_q[16];
#pragma unroll
    for (int i = 0; i < 16; ++i) { st_s[i] = 0.f; st_q[i] = 0.f; }

#pragma unroll
    for (int mt = 0; mt < 2; ++mt) {
#pragma unroll
        for (int half = 0; half < 2; ++half) {
            int r = wm + mt * 16 + g + half * 8;
            if (m0 + r >= n_rows) continue;
            size_t grow = (size_t)(row_start + m0 + r);
            float4 b03 = *(const float4*)(g_Bsum + grow * 8);
            float4 b47 = *(const float4*)(g_Bsum + grow * 8 + 4);
            float bs[6] = {b03.x, b03.y, b03.z, b03.w, b47.x, b47.y};
#pragma unroll
            for (int nt = 0; nt < 8; ++nt) {
                int cl = wn + nt * 8 + tq * 2;
                float v0 = acc[mt][nt][half * 2 + 0] + s_bias[cl];
                float v1 = acc[mt][nt][half * 2 + 1] + s_bias[cl + 1];
#pragma unroll
                for (int j = 0; j < 6; ++j) {
                    v0 = fmaf(bs[j], s_wbot[j][cl],     v0);
                    v1 = fmaf(bs[j], s_wbot[j][cl + 1], v1);
                }
                v0 = fmaxf(v0, 0.f);
                v1 = fmaxf(v1, 0.f);
                *(float2*)(g_pre + grow * 256 + cl) = make_float2(v0, v1);
                st_s[nt * 2]     += v0;
                st_s[nt * 2 + 1] += v1;
                st_q[nt * 2]     = fmaf(v0, v0, st_q[nt * 2]);
                st_q[nt * 2 + 1] = fmaf(v1, v1, st_q[nt * 2 + 1]);
            }
        }
    }
    // reduce over the 8 row-lane groups within the warp
#pragma unroll
    for (int off = 4; off < 32; off <<= 1) {
#pragma unroll
        for (int i = 0; i < 16; ++i) {
            st_s[i] += __shfl_xor_sync(0xffffffffu, st_s[i], off);
            st_q[i] += __shfl_xor_sync(0xffffffffu, st_q[i], off);
        }
    }
    __syncthreads();               // pipeline smem dead; begin stats merge
    // each warp (wm-index = warp&3) owns disjoint cols [wn, wn+64)
    if (lane < 4) {
#pragma unroll
        for (int nt = 0; nt < 8; ++nt) {
            int cl = wn + nt * 8 + lane * 2;
            s_ws[warp & 3][cl]     = st_s[nt * 2];
            s_ws[warp & 3][cl + 1] = st_s[nt * 2 + 1];
            s_wq[warp & 3][cl]     = st_q[nt * 2];
            s_wq[warp & 3][cl + 1] = st_q[nt * 2 + 1];
        }
    }
    __syncthreads();
    if (tid < 256) {
        float s = s_ws[0][tid] + s_ws[1][tid] + s_ws[2][tid] + s_ws[3][tid];
        float q = s_wq[0][tid] + s_wq[1][tid] + s_wq[2][tid] + s_wq[3][tid];
        g_part[blockIdx.x * 256 + tid]        = s;
        g_part[QOFF + blockIdx.x * 256 + tid] = q;
    }
}

// ---------------------------------------------------------------------------
// 3) stats reduction (deterministic)
// ---------------------------------------------------------------------------
__global__ void __launch_bounds__(256) stats_reduce(int n_slots)
{
    const int b = blockIdx.x, t = threadIdx.x;
    const int chunk = (n_slots + 63) >> 6;
    int p0 = b * chunk;
    int p1 = p0 + chunk; if (p1 > n_slots) p1 = n_slots;
    float s = 0.f, q = 0.f;
    for (int p = p0; p < p1; ++p) {
        s += g_part[p * 256 + t];
        q += g_part[QOFF + p * 256 + t];
    }
    g_part2[b * 256 + t] = s;
    g_part2[64 * 256 + b * 256 + t] = q;
}

__global__ void finalize_kernel(const float* __restrict__ bnw,
                                const float* __restrict__ bnb, int n_atoms)
{
    const int t = threadIdx.x;
    float s = 0.f, q = 0.f;
    for (int p = 0; p < 64; ++p) {
        s += g_part2[p * 256 + t];
        q += g_part2[64 * 256 + p * 256 + t];
    }
    const float inv = 1.f / (float)n_atoms;
    const float mean = s * inv;
    const float var  = q * inv - mean * mean;
    const float a = bnw[t] * rsqrtf(var + 1e-5f);
    g_scale[t] = a;
    g_shift[t] = bnb[t] - mean * a;
}

// ---------------------------------------------------------------------------
// 4) normalize
// ---------------------------------------------------------------------------
__global__ void __launch_bounds__(256) norm_kernel(float* __restrict__ out,
                                                   int total4)
{
    __shared__ float sc[256], sh[256];
    sc[threadIdx.x] = g_scale[threadIdx.x];
    sh[threadIdx.x] = g_shift[threadIdx.x];
    __syncthreads();
    for (int i = blockIdx.x * blockDim.x + threadIdx.x; i < total4;
         i += gridDim.x * blockDim.x) {
        float4 v = *(const float4*)(g_pre + (size_t)i * 4);
        int c = (i & 63) * 4;
        v.x = fmaf(v.x, sc[c],     sh[c]);
        v.y = fmaf(v.y, sc[c + 1], sh[c + 1]);
        v.z = fmaf(v.z, sc[c + 2], sh[c + 2]);
        v.w = fmaf(v.w, sc[c + 3], sh[c + 3]);
        *(float4*)(out + (size_t)i * 4) = v;
    }
}

// ---------------------------------------------------------------------------
extern "C" void kernel_launch(void* const* d_in, const int* in_sizes, int n_in,
                              void* d_out, int out_size)
{
    const float* af = (const float*)d_in[0];
    const float* bf = (const float*)d_in[1];

    int a_idx[5], b_idx[5];
    const bool interleaved = (in_sizes[3] == in_sizes[2]);
    for (int d = 0; d < 5; ++d) {
        if (interleaved) { a_idx[d] = 2 + 2 * d; b_idx[d] = 3 + 2 * d; }
        else             { a_idx[d] = 2 + d;     b_idx[d] = 7 + d;     }
    }

    const float* Wself = (const float*)d_in[12];
    const float* bias  = (const float*)d_in[13];
    const float* Wdeg[5];
    for (int d = 0; d < 5; ++d) Wdeg[d] = (const float*)d_in[14 + d];
    const float* bnw = (const float*)d_in[19];
    const float* bnb = (const float*)d_in[20];

    const int n_atoms = in_sizes[0] / 256;

    GArgs ga;
    SegArgs sa;
    int o = 0;
    ga.blkA[0] = 0; ga.blkB[0] = 0; sa.blk[0] = 0;
    for (int d = 0; d < 5; ++d) {
        ga.an[d]  = (const int*)d_in[a_idx[d]];
        ga.bn[d]  = (const int*)d_in[b_idx[d]];
        ga.nd[d]  = in_sizes[a_idx[d]] / (d + 1);
        ga.off[d] = o;
        sa.Worig[d] = Wdeg[d];
        sa.nd[d]  = ga.nd[d];
        sa.off[d] = o;
        o += ga.nd[d];
        ga.blkA[d + 1] = ga.blkA[d] + (ga.nd[d] + 3) / 4;
        ga.blkB[d + 1] = ga.blkB[d] + (ga.nd[d] + 255) / 256;
        sa.blk[d + 1]  = sa.blk[d] + (ga.nd[d] + 127) / 128;
    }

    cudaFuncSetAttribute(gemm_mma, cudaFuncAttributeMaxDynamicSharedMemorySize,
                         196608);

    // 0) weight prep
    prep_kernel<<<6 * 65536 / 256, 256>>>(Wself, Wdeg[0], Wdeg[1], Wdeg[2],
                                          Wdeg[3], Wdeg[4]);

    // 1) all gathers in one launch
    gather_all<<<ga.blkA[5] + ga.blkB[5], 256>>>(af, bf, ga);

    // 2) merged GEMM (512 threads, fused per-CTA bn stats)
    gemm_mma<<<sa.blk[5], 512, 196608>>>(af, bias, sa);

    // 3) batchnorm stats reduction
    stats_reduce<<<64, 256>>>(sa.blk[5]);
    finalize_kernel<<<1, 256>>>(bnw, bnb, n_atoms);

    // 4) normalize
    norm_kernel<<<1184, 256>>>((float*)d_out, n_atoms * 64);
}

// round 16
// speedup vs baseline: 1.2589x; 1.2589x over previous
#include <cuda_runtime.h>
#include <cstdint>

// ---------------------------------------------------------------------------
// GraphConvLayer — mma.sync tf32, 4-deep cp.async, 512-thread GEMM (no-spill)
//   0) prep_kernel   : transpose weights -> tf32 [n][k]
//   1) gather_all    : all-degree atom-sum + bond-sum (single launch)
//   2) gemm_mma      : ONE launch, 5 segments; 128x256x512 per CTA,
//                      16 warps (4/SMSP), warp tile 32x64, 4-slot cp.async,
//                      bias+bond epilogue + ReLU -> g_pre  (NO fused stats
//                      -> regs fit the 128/thread cap, no local spills)
//   3) stats_kernel / stats_reduce / finalize : deterministic batchnorm
//   4) norm_kernel   : g_pre -> d_out
// ---------------------------------------------------------------------------

#define NATOMS_MAX 200000
#define NSLOTS 256
#define QOFF (NSLOTS * 256)

__device__ float g_Asum[(size_t)NATOMS_MAX * 256];
__device__ float g_Bsum[(size_t)NATOMS_MAX * 8];
__device__ float g_pre [(size_t)NATOMS_MAX * 256];
__device__ float g_Wt_self[256 * 256];        // [n][k], tf32-rounded
__device__ float g_Wt_deg [5 * 256 * 256];    // [d][n][k]
__device__ float g_part [2 * NSLOTS * 256];
__device__ float g_scale[256];
__device__ float g_shift[256];

// ---------------- helpers ----------------
__device__ __forceinline__ uint32_t smem_u32(const void* p) {
    uint32_t a;
    asm("{ .reg .u64 t; cvta.to.shared.u64 t, %1; cvt.u32.u64 %0, t; }"
        : "=r"(a) : "l"(p));
    return a;
}
__device__ __forceinline__ uint32_t f2tf(float f) {
    uint32_t u;
    asm("cvt.rna.tf32.f32 %0, %1;" : "=r"(u) : "f"(f));
    return u;
}
__device__ __forceinline__ void cp_async16(uint32_t saddr, const void* gptr) {
    size_t g = __cvta_generic_to_global(gptr);
    asm volatile("cp.async.cg.shared.global [%0], [%1], 16;"
                 :: "r"(saddr), "l"(g));
}
#define CP_COMMIT() asm volatile("cp.async.commit_group;" ::: "memory")
#define CP_WAIT2()  asm volatile("cp.async.wait_group 2;" ::: "memory")

__device__ __forceinline__ void ldm_x4(uint32_t* r, uint32_t addr) {
    asm volatile("ldmatrix.sync.aligned.m8n8.x4.shared.b16 {%0,%1,%2,%3}, [%4];"
                 : "=r"(r[0]), "=r"(r[1]), "=r"(r[2]), "=r"(r[3]) : "r"(addr));
}
__device__ __forceinline__ void mma_tf32(float* c, const uint32_t* a,
                                         uint32_t b0, uint32_t b1) {
    asm volatile(
        "mma.sync.aligned.m16n8k8.row.col.f32.tf32.tf32.f32 "
        "{%0,%1,%2,%3}, {%4,%5,%6,%7}, {%8,%9}, {%0,%1,%2,%3};"
        : "+f"(c[0]), "+f"(c[1]), "+f"(c[2]), "+f"(c[3])
        : "r"(a[0]), "r"(a[1]), "r"(a[2]), "r"(a[3]), "r"(b0), "r"(b1));
}

// ---------------------------------------------------------------------------
// 0) prep: Wt[n][k] = tf32(W[k][n])
// ---------------------------------------------------------------------------
__global__ void __launch_bounds__(256) prep_kernel(
    const float* __restrict__ Ws,
    const float* __restrict__ W1, const float* __restrict__ W2,
    const float* __restrict__ W3, const float* __restrict__ W4,
    const float* __restrict__ W5)
{
    const float* Wd[5] = {W1, W2, W3, W4, W5};
    int id = blockIdx.x * 256 + threadIdx.x;
    if (id < 65536) {
        int n = id >> 8, k = id & 255;
        g_Wt_self[id] = __uint_as_float(f2tf(__ldg(Ws + k * 256 + n)));
    } else if (id < 6 * 65536) {
        int t = id - 65536;
        int d = t >> 16, rr = t & 65535;
        int n = rr >> 8, k = rr & 255;
        g_Wt_deg[t] = __uint_as_float(f2tf(__ldg(Wd[d] + k * 256 + n)));
    }
}

// ---------------------------------------------------------------------------
// 1) gather (single launch, block-range dispatch over 5+5 segments)
// ---------------------------------------------------------------------------
struct GArgs {
    const int* an[5];
    const int* bn[5];
    int nd[5];
    int off[5];
    int blkA[6];
    int blkB[6];
};

template <int D>
__device__ __forceinline__ void do_atoms(const float* __restrict__ af,
                                         const int* __restrict__ anbr,
                                         int row_start, int n, int lb)
{
    int gid = lb * 256 + threadIdx.x;
    int atom = gid >> 6;
    if (atom >= n) return;
    int c = gid & 63;
    int idx[D];
#pragma unroll
    for (int s = 0; s < D; ++s) idx[s] = __ldg(anbr + atom * D + s);
    float4 acc = make_float4(0.f, 0.f, 0.f, 0.f);
#pragma unroll
    for (int s = 0; s < D; ++s) {
        float4 v = __ldg((const float4*)af + (size_t)idx[s] * 64 + c);
        acc.x += v.x; acc.y += v.y; acc.z += v.z; acc.w += v.w;
    }
    acc.x = __uint_as_float(f2tf(acc.x));
    acc.y = __uint_as_float(f2tf(acc.y));
    acc.z = __uint_as_float(f2tf(acc.z));
    acc.w = __uint_as_float(f2tf(acc.w));
    ((float4*)g_Asum)[(size_t)(row_start + atom) * 64 + c] = acc;
}

template <int D>
__device__ __forceinline__ void do_bonds(const float* __restrict__ bf,
                                         const int* __restrict__ bnbr,
                                         int row_start, int n, int lb)
{
    int atom = lb * 256 + threadIdx.x;
    if (atom >= n) return;
    float s[6] = {0.f, 0.f, 0.f, 0.f, 0.f, 0.f};
#pragma unroll
    for (int j = 0; j < D; ++j) {
        int idx = __ldg(bnbr + atom * D + j);
        const float* row = bf + (size_t)idx * 6;
#pragma unroll
        for (int q = 0; q < 6; ++q) s[q] += __ldg(row + q);
    }
    float* o = g_Bsum + (size_t)(row_start + atom) * 8;
    *(float4*)o       = make_float4(s[0], s[1], s[2], s[3]);
    *(float4*)(o + 4) = make_float4(s[4], s[5], 0.f, 0.f);
}

__global__ void __launch_bounds__(256) gather_all(
    const float* __restrict__ af, const float* __restrict__ bf, GArgs ga)
{
    int bid = blockIdx.x;
    if (bid < ga.blkA[5]) {
        int d = 0;
        while (bid >= ga.blkA[d + 1]) ++d;
        int lb = bid - ga.blkA[d];
        switch (d) {
        case 0: do_atoms<1>(af, ga.an[0], ga.off[0], ga.nd[0], lb); break;
        case 1: do_atoms<2>(af, ga.an[1], ga.off[1], ga.nd[1], lb); break;
        case 2: do_atoms<3>(af, ga.an[2], ga.off[2], ga.nd[2], lb); break;
        case 3: do_atoms<4>(af, ga.an[3], ga.off[3], ga.nd[3], lb); break;
        default: do_atoms<5>(af, ga.an[4], ga.off[4], ga.nd[4], lb); break;
        }
    } else {
        int bb = bid - ga.blkA[5];
        int d = 0;
        while (bb >= ga.blkB[d + 1]) ++d;
        int lb = bb - ga.blkB[d];
        switch (d) {
        case 0: do_bonds<1>(bf, ga.bn[0], ga.off[0], ga.nd[0], lb); break;
        case 1: do_bonds<2>(bf, ga.bn[1], ga.off[1], ga.nd[1], lb); break;
        case 2: do_bonds<3>(bf, ga.bn[2], ga.off[2], ga.nd[2], lb); break;
        case 3: do_bonds<4>(bf, ga.bn[3], ga.off[3], ga.nd[3], lb); break;
        default: do_bonds<5>(bf, ga.bn[4], ga.off[4], ga.nd[4], lb); break;
        }
    }
}

// ---------------------------------------------------------------------------
// 2) merged GEMM, 512 threads: CTA 128(M) x 256(N), K=512, 16 stages of 32.
//    16 warps = 4(M) x 4(N); warp tile 32x64; m16n8k8 tf32 (ldmatrix b16).
//    4-slot cp.async (distance 3); smem A 4x16KB @ uS, B 4x32KB @ uS+65536.
//    No fused stats -> ~115 regs/thread, no spills at the 128-reg cap.
// ---------------------------------------------------------------------------
struct SegArgs {
    const float* Worig[5];   // original [262][256] (bond rows)
    int blk[6];              // cumulative CTA offsets per segment
    int off[5];
    int nd[5];
};

__device__ __forceinline__ void issue_stage(
    uint32_t uS, int slot, int kt,
    const float* __restrict__ af, const float* __restrict__ WtD,
    int tid, int m0, int row_start, int n_rows)
{
    const int lrow = tid >> 3;          // 0..63
    const int lchk = tid & 7;
    const int kk = (kt * 32) & 255;

    const float* Ab = (kt < 8) ? af : g_Asum;
    uint32_t dA = uS + (uint32_t)slot * 16384;
#pragma unroll
    for (int p = 0; p < 2; ++p) {
        int r = lrow + p * 64;
        int rg = m0 + r; if (rg >= n_rows) rg = n_rows - 1;
        const char* src = (const char*)(Ab + (size_t)(row_start + rg) * 256 + kk)
                          + lchk * 16;
        cp_async16(dA + (uint32_t)r * 128 + (uint32_t)((lchk ^ (r & 7)) << 4), src);
    }
    const float* Bb = (kt < 8) ? g_Wt_self : WtD;
    uint32_t dB = uS + 65536u + (uint32_t)slot * 32768;
#pragma unroll
    for (int p = 0; p < 4; ++p) {
        int r = lrow + p * 64;
        const char* src = (const char*)(Bb + (size_t)r * 256 + kk) + lchk * 16;
        cp_async16(dB + (uint32_t)r * 128 + (uint32_t)((lchk ^ (r & 7)) << 4), src);
    }
}

__global__ void __launch_bounds__(512, 1) gemm_mma(
    const float* __restrict__ af, const float* __restrict__ bias, SegArgs sa)
{
    extern __shared__ float dsm[];          // 4*(16KB A) + 4*(32KB B) = 192KB
    __shared__ float s_wbot[6][256];
    __shared__ float s_bias[256];

    // ---- segment dispatch ----
    int deg = 0;
    while ((int)blockIdx.x >= sa.blk[deg + 1]) ++deg;
    const int m0 = (blockIdx.x - sa.blk[deg]) * 128;
    const int row_start = sa.off[deg];
    const int n_rows = sa.nd[deg];
    const float* __restrict__ Worig = sa.Worig[deg];
    const float* __restrict__ WtD = g_Wt_deg + (size_t)deg * 65536;

    const uint32_t uS = smem_u32(dsm);
    const int tid = threadIdx.x;
    const int warp = tid >> 5, lane = tid & 31;
    const int wm = (warp & 3) * 32;         // M warp group
    const int wn = (warp >> 2) * 64;        // N warp group

    if (tid < 256) s_bias[tid] = __ldg(bias + tid);
#pragma unroll
    for (int j = 0; j < 3; ++j) {
        int jj2 = j * 2 + (tid >> 8);
        s_wbot[jj2][tid & 255] = __ldg(Worig + (size_t)(256 + jj2) * 256 + (tid & 255));
    }

    float acc[2][8][4];
#pragma unroll
    for (int a = 0; a < 2; ++a)
#pragma unroll
        for (int b = 0; b < 8; ++b)
#pragma unroll
            for (int e = 0; e < 4; ++e) acc[a][b][e] = 0.f;

    const int jj = lane >> 3, rr = lane & 7;
    uint32_t rowA[2], rowB[4];
#pragma unroll
    for (int mt = 0; mt < 2; ++mt)
        rowA[mt] = (uint32_t)(wm + mt * 16 + (jj & 1) * 8 + rr) * 128;
#pragma unroll
    for (int np = 0; np < 4; ++np)
        rowB[np] = (uint32_t)(wn + np * 16 + (jj >> 1) * 8 + rr) * 128;
    const int cjA = jj >> 1, cjB = jj & 1;

    issue_stage(uS, 0, 0, af, WtD, tid, m0, row_start, n_rows); CP_COMMIT();
    issue_stage(uS, 1, 1, af, WtD, tid, m0, row_start, n_rows); CP_COMMIT();
    issue_stage(uS, 2, 2, af, WtD, tid, m0, row_start, n_rows); CP_COMMIT();

    for (int kt = 0; kt < 16; ++kt) {
        CP_WAIT2();
        __syncthreads();
        if (kt + 3 < 16)
            issue_stage(uS, (kt + 3) & 3, kt + 3, af, WtD, tid, m0, row_start, n_rows);
        CP_COMMIT();

        const uint32_t baseA = uS + (uint32_t)(kt & 3) * 16384;
        const uint32_t baseB = uS + 65536u + (uint32_t)(kt & 3) * 32768;
#pragma unroll
        for (int k8 = 0; k8 < 4; ++k8) {
            uint32_t aF[2][4], bF[4][4];
            const uint32_t ca = (uint32_t)(((2 * k8 + cjA) ^ rr) << 4);
            const uint32_t cb = (uint32_t)(((2 * k8 + cjB) ^ rr) << 4);
#pragma unroll
            for (int mt = 0; mt < 2; ++mt) ldm_x4(aF[mt], baseA + rowA[mt] + ca);
#pragma unroll
            for (int np = 0; np < 4; ++np) ldm_x4(bF[np], baseB + rowB[np] + cb);
#pragma unroll
            for (int mt = 0; mt < 2; ++mt)
#pragma unroll
                for (int np = 0; np < 4; ++np) {
                    mma_tf32(acc[mt][2 * np],     aF[mt], bF[np][0], bF[np][1]);
                    mma_tf32(acc[mt][2 * np + 1], aF[mt], bF[np][2], bF[np][3]);
                }
        }
    }

    // ---- epilogue: + bias + Bsum@wbot, ReLU, store ----
    const int g = lane >> 2, tq = lane & 3;
#pragma unroll
    for (int mt = 0; mt < 2; ++mt) {
#pragma unroll
        for (int half = 0; half < 2; ++half) {
            int r = wm + mt * 16 + g + half * 8;
            if (m0 + r >= n_rows) continue;
            size_t grow = (size_t)(row_start + m0 + r);
            float4 b03 = *(const float4*)(g_Bsum + grow * 8);
            float4 b47 = *(const float4*)(g_Bsum + grow * 8 + 4);
            float bs[6] = {b03.x, b03.y, b03.z, b03.w, b47.x, b47.y};
#pragma unroll
            for (int nt = 0; nt < 8; ++nt) {
                int cl = wn + nt * 8 + tq * 2;
                float v0 = acc[mt][nt][half * 2 + 0] + s_bias[cl];
                float v1 = acc[mt][nt][half * 2 + 1] + s_bias[cl + 1];
#pragma unroll
                for (int j = 0; j < 6; ++j) {
                    v0 = fmaf(bs[j], s_wbot[j][cl],     v0);
                    v1 = fmaf(bs[j], s_wbot[j][cl + 1], v1);
                }
                v0 = fmaxf(v0, 0.f);
                v1 = fmaxf(v1, 0.f);
                *(float2*)(g_pre + grow * 256 + cl) = make_float2(v0, v1);
            }
        }
    }
}

// ---------------------------------------------------------------------------
// 3) batchnorm stats (deterministic, coalesced float4) + finalize
// ---------------------------------------------------------------------------
__global__ void __launch_bounds__(256) stats_kernel(int n_atoms)
{
    const int c4 = threadIdx.x & 63;   // float4 column
    const int rl = threadIdx.x >> 6;   // 0..3 row lane
    const int p = blockIdx.x;
    const int chunk = (n_atoms + NSLOTS - 1) / NSLOTS;
    int r0 = p * chunk;
    int r1 = r0 + chunk; if (r1 > n_atoms) r1 = n_atoms;

    float4 s  = make_float4(0.f, 0.f, 0.f, 0.f);
    float4 s2 = make_float4(0.f, 0.f, 0.f, 0.f);
    for (int r = r0 + rl; r < r1; r += 4) {
        float4 v = *(const float4*)(g_pre + (size_t)r * 256 + c4 * 4);
        s.x += v.x; s.y += v.y; s.z += v.z; s.w += v.w;
        s2.x = fmaf(v.x, v.x, s2.x); s2.y = fmaf(v.y, v.y, s2.y);
        s2.z = fmaf(v.z, v.z, s2.z); s2.w = fmaf(v.w, v.w, s2.w);
    }
    __shared__ float4 red[2][4][64];
    red[0][rl][c4] = s;
    red[1][rl][c4] = s2;
    __syncthreads();
    if (rl == 0) {
        float4 a = red[0][0][c4], b = red[1][0][c4];
#pragma unroll
        for (int q = 1; q < 4; ++q) {
            float4 x = red[0][q][c4], y = red[1][q][c4];
            a.x += x.x; a.y += x.y; a.z += x.z; a.w += x.w;
            b.x += y.x; b.y += y.y; b.z += y.z; b.w += y.w;
        }
        *(float4*)(g_part + p * 256 + c4 * 4) = a;
        *(float4*)(g_part + QOFF + p * 256 + c4 * 4) = b;
    }
}

__global__ void finalize_kernel(const float* __restrict__ bnw,
                                const float* __restrict__ bnb, int n_atoms)
{
    const int t = threadIdx.x;
    float s = 0.f, q = 0.f;
    for (int p = 0; p < NSLOTS; ++p) {
        s += g_part[p * 256 + t];
        q += g_part[QOFF + p * 256 + t];
    }
    const float inv = 1.f / (float)n_atoms;
    const float mean = s * inv;
    const float var  = q * inv - mean * mean;
    const float a = bnw[t] * rsqrtf(var + 1e-5f);
    g_scale[t] = a;
    g_shift[t] = bnb[t] - mean * a;
}

// ---------------------------------------------------------------------------
// 4) normalize
// ---------------------------------------------------------------------------
__global__ void __launch_bounds__(256) norm_kernel(float* __restrict__ out,
                                                   int total4)
{
    __shared__ float sc[256], sh[256];
    sc[threadIdx.x] = g_scale[threadIdx.x];
    sh[threadIdx.x] = g_shift[threadIdx.x];
    __syncthreads();
    for (int i = blockIdx.x * blockDim.x + threadIdx.x; i < total4;
         i += gridDim.x * blockDim.x) {
        float4 v = *(const float4*)(g_pre + (size_t)i * 4);
        int c = (i & 63) * 4;
        v.x = fmaf(v.x, sc[c],     sh[c]);
        v.y = fmaf(v.y, sc[c + 1], sh[c + 1]);
        v.z = fmaf(v.z, sc[c + 2], sh[c + 2]);
        v.w = fmaf(v.w, sc[c + 3], sh[c + 3]);
        *(float4*)(out + (size_t)i * 4) = v;
    }
}

// ---------------------------------------------------------------------------
extern "C" void kernel_launch(void* const* d_in, const int* in_sizes, int n_in,
                              void* d_out, int out_size)
{
    const float* af = (const float*)d_in[0];
    const float* bf = (const float*)d_in[1];

    int a_idx[5], b_idx[5];
    const bool interleaved = (in_sizes[3] == in_sizes[2]);
    for (int d = 0; d < 5; ++d) {
        if (interleaved) { a_idx[d] = 2 + 2 * d; b_idx[d] = 3 + 2 * d; }
        else             { a_idx[d] = 2 + d;     b_idx[d] = 7 + d;     }
    }

    const float* Wself = (const float*)d_in[12];
    const float* bias  = (const float*)d_in[13];
    const float* Wdeg[5];
    for (int d = 0; d < 5; ++d) Wdeg[d] = (const float*)d_in[14 + d];
    const float* bnw = (const float*)d_in[19];
    const float* bnb = (const float*)d_in[20];

    const int n_atoms = in_sizes[0] / 256;

    GArgs ga;
    SegArgs sa;
    int o = 0;
    ga.blkA[0] = 0; ga.blkB[0] = 0; sa.blk[0] = 0;
    for (int d = 0; d < 5; ++d) {
        ga.an[d]  = (const int*)d_in[a_idx[d]];
        ga.bn[d]  = (const int*)d_in[b_idx[d]];
        ga.nd[d]  = in_sizes[a_idx[d]] / (d + 1);
        ga.off[d] = o;
        sa.Worig[d] = Wdeg[d];
        sa.nd[d]  = ga.nd[d];
        sa.off[d] = o;
        o += ga.nd[d];
        ga.blkA[d + 1] = ga.blkA[d] + (ga.nd[d] + 3) / 4;
        ga.blkB[d + 1] = ga.blkB[d] + (ga.nd[d] + 255) / 256;
        sa.blk[d + 1]  = sa.blk[d] + (ga.nd[d] + 127) / 128;
    }

    cudaFuncSetAttribute(gemm_mma, cudaFuncAttributeMaxDynamicSharedMemorySize,
                         196608);

    // 0) weight prep
    prep_kernel<<<6 * 65536 / 256, 256>>>(Wself, Wdeg[0], Wdeg[1], Wdeg[2],
                                          Wdeg[3], Wdeg[4]);

    // 1) all gathers in one launch
    gather_all<<<ga.blkA[5] + ga.blkB[5], 256>>>(af, bf, ga);

    // 2) merged GEMM (512 threads, no fused stats -> no spills)
    gemm_mma<<<sa.blk[5], 512, 196608>>>(af, bias, sa);

    // 3) batchnorm stats
    stats_kernel<<<NSLOTS, 256>>>(n_atoms);
    finalize_kernel<<<1, 256>>>(bnw, bnb, n_atoms);

    // 4) normalize
    norm_kernel<<<1184, 256>>>((float*)d_out, n_atoms * 64);
}